// round 1
// baseline (speedup 1.0000x reference)
#include <cuda_runtime.h>
#include <math.h>

#define GD 160
#define GH 160
#define GW 160
#define NP 25000
#define RADF 3.0f
#define PATCHN 20

__global__ __launch_bounds__(256) void splat_kernel(
    const float* __restrict__ centers,     // [N,3]  (z,y,x) in [0,1]
    const float* __restrict__ log_scales,  // [N,3]
    const float* __restrict__ quats,       // [N,4]
    const float* __restrict__ rho,         // [N,2]
    float* __restrict__ out)               // [GD*GH*GW*2]
{
    const int n = blockIdx.x;
    if (n >= NP) return;

    // ---- per-point setup (redundant per thread; loads hit L1/L2) ----
    const float cz = centers[n * 3 + 0] * (float)(GD - 1);
    const float cy = centers[n * 3 + 1] * (float)(GH - 1);
    const float cx = centers[n * 3 + 2] * (float)(GW - 1);

    // precise expf: these feed floor/ceil integer bounds, must match reference
    const float s0 = expf(log_scales[n * 3 + 0]);
    const float s1 = expf(log_scales[n * 3 + 1]);
    const float s2 = expf(log_scales[n * 3 + 2]);

    const float r0v = rho[n * 2 + 0];
    const float r1v = rho[n * 2 + 1];

    const float smax = fmaxf(s0, fmaxf(s1, s2));
    const float rad  = smax * RADF;
    const float amp  = sqrtf(r0v * r0v + r1v * r1v);
    if (!(amp >= 1e-6f && rad >= 1e-3f)) return;

    // quaternion -> rotation
    float qw = quats[n * 4 + 0], qx = quats[n * 4 + 1];
    float qy = quats[n * 4 + 2], qz = quats[n * 4 + 3];
    {
        float nq = sqrtf(qw * qw + qx * qx + qy * qy + qz * qz);
        nq = fmaxf(nq, 1e-6f);
        float inq = 1.0f / nq;
        qw *= inq; qx *= inq; qy *= inq; qz *= inq;
    }
    const float ww = qw * qw, xx = qx * qx, yy = qy * qy, zz = qz * qz;
    const float wx = qw * qx, wy = qw * qy, wz = qw * qz;
    const float xy = qx * qy, xz = qx * qz, yz = qy * qz;

    const float R00 = ww + xx - yy - zz, R01 = 2.f * (xy - wz), R02 = 2.f * (xz + wy);
    const float R10 = 2.f * (xy + wz),   R11 = ww - xx + yy - zz, R12 = 2.f * (yz - wx);
    const float R20 = 2.f * (xz - wy),   R21 = 2.f * (yz + wx),   R22 = ww - xx - yy + zz;

    const float c0 = fmaxf(s0, 1e-4f), c1s = fmaxf(s1, 1e-4f), c2s = fmaxf(s2, 1e-4f);
    const float i0 = 1.0f / (c0 * c0), i1 = 1.0f / (c1s * c1s), i2 = 1.0f / (c2s * c2s);

    // precision matrix P = R diag(i) R^T  (symmetric, 6 unique)
    const float p00 = R00 * R00 * i0 + R01 * R01 * i1 + R02 * R02 * i2;
    const float p11 = R10 * R10 * i0 + R11 * R11 * i1 + R12 * R12 * i2;
    const float p22 = R20 * R20 * i0 + R21 * R21 * i1 + R22 * R22 * i2;
    const float p01 = R00 * R10 * i0 + R01 * R11 * i1 + R02 * R12 * i2;
    const float p02 = R00 * R20 * i0 + R01 * R21 * i1 + R02 * R22 * i2;
    const float p12 = R10 * R20 * i0 + R11 * R21 * i1 + R12 * R22 * i2;

    // integer loop bounds replicating the reference mask exactly:
    // idx = base + off (off<20), idx>=0, idx<dim, idx<=hi
    const int bz = (int)floorf(cz - rad), by = (int)floorf(cy - rad), bx = (int)floorf(cx - rad);
    const int hz = (int)ceilf(cz + rad),  hy = (int)ceilf(cy + rad),  hx = (int)ceilf(cx + rad);

    const int lz = max(bz, 0), ly = max(by, 0), lx = max(bx, 0);
    const int uz = min(min(hz, GD - 1), bz + PATCHN - 1);
    const int uy = min(min(hy, GH - 1), by + PATCHN - 1);
    const int ux = min(min(hx, GW - 1), bx + PATCHN - 1);
    if (lz > uz || ly > uy || lx > ux) return;

    const int ny = uy - ly + 1;
    const int nx = ux - lx + 1;
    const int nyx = ny * nx;

    for (int t = threadIdx.x; t < nyx; t += blockDim.x) {
        const int iy = t / nx;
        const int ix = t - iy * nx;
        const int Y = ly + iy;
        const int X = lx + ix;
        const float dy = (float)Y - cy;
        const float dx = (float)X - cx;

        // e(z) = eyx + dz*(cl + p00*dz)
        const float eyx = p11 * dy * dy + (p22 * dx + 2.0f * p12 * dy) * dx;
        const float cl  = 2.0f * (p01 * dy + p02 * dx);
        const int linYX = Y * GW + X;

        for (int Z = lz; Z <= uz; ++Z) {
            const float dz = (float)Z - cz;
            const float e  = fmaf(dz, fmaf(p00, dz, cl), eyx);
            const float w  = __expf(-0.5f * e);
            const float w0 = w * r0v;
            const float w1 = w * r1v;
            const size_t lin2 = 2ull * (size_t)(Z * (GH * GW) + linYX);
            asm volatile("red.global.add.v2.f32 [%0], {%1, %2};"
                         :: "l"(out + lin2), "f"(w0), "f"(w1)
                         : "memory");
        }
    }
}

extern "C" void kernel_launch(void* const* d_in, const int* in_sizes, int n_in,
                              void* d_out, int out_size) {
    const float* centers    = (const float*)d_in[0];
    const float* log_scales = (const float*)d_in[1];
    const float* quats      = (const float*)d_in[2];
    const float* rho        = (const float*)d_in[3];
    float* out = (float*)d_out;

    // output is poisoned; zero it (graph-capturable async memset, same stream)
    cudaMemsetAsync(out, 0, (size_t)out_size * sizeof(float), 0);

    splat_kernel<<<NP, 256>>>(centers, log_scales, quats, rho, out);
}